// round 7
// baseline (speedup 1.0000x reference)
#include <cuda_runtime.h>
#include <math.h>

#define HDIM 512
#define BSZ  128
#define TIN  256
#define MLEN 128
#define VOC  32
#define BH   (BSZ*HDIM)
#define B2H  (BSZ*2*HDIM)
#define NBLK 148
#define NTHR 512

typedef unsigned long long u64;

// ---------------- device scratch ----------------
__device__ float g_y0[TIN*BH];
__device__ float g_enc[TIN*BH];
__device__ float g_q[MLEN*BH];
__device__ float g_rnn[MLEN*B2H];
__device__ float g_h0[MLEN*BH];
__device__ float g_h1[MLEN*BH];
__device__ int   g_tok[(MLEN+1)*BSZ];
__device__ unsigned g_arrive;
__device__ volatile unsigned g_release;

// ---------------- shared memory ----------------
struct SmG   { float hs[2][32][36]; float ws[2][48][36]; };   // 11.5 KB x2 buf = 23 KB
struct SmPair{ SmG g[2]; };                                   // 46 KB (one per k-group)
struct SmC   { u64 acc[256][8]; };                            // 16 KB combine (aliases SmPair)
struct SmA   { float q[HDIM]; float sc[TIN]; float red[16]; };
struct SmL   { float hrow[HDIM]; float lg[VOC]; };
union  SmU   { SmPair p; SmC c; SmA a; SmL l; };

// ---------------- packed f32x2 helpers ----------------
__device__ __forceinline__ u64 fma2(u64 a, u64 b, u64 c)
{
    u64 d;
    asm("fma.rn.f32x2 %0, %1, %2, %3;" : "=l"(d) : "l"(a), "l"(b), "l"(c));
    return d;
}
__device__ __forceinline__ u64 add2(u64 a, u64 b)
{
    u64 d;
    asm("add.rn.f32x2 %0, %1, %2;" : "=l"(d) : "l"(a), "l"(b));
    return d;
}
__device__ __forceinline__ float red2(u64 a)
{
    float lo, hi;
    asm("mov.b64 {%0, %1}, %2;" : "=f"(lo), "=f"(hi) : "l"(a));
    return lo + hi;
}

// named barrier for one 256-thread k-group
__device__ __forceinline__ void barg(int grp)
{
    asm volatile("bar.sync %0, %1;" :: "r"(grp + 1), "r"(256) : "memory");
}

// ---------------- software grid barrier ----------------
__device__ __forceinline__ void gsync(unsigned &phase)
{
    __threadfence();
    __syncthreads();
    phase++;
    if (threadIdx.x == 0) {
        unsigned p = phase;
        unsigned old = atomicAdd(&g_arrive, 1u);
        if (old == p * (unsigned)NBLK - 1u) {
            g_release = p;
        } else {
            while (g_release < p) { }
        }
        __threadfence();
    }
    __syncthreads();
}

// ---------------- pipelined K-major GEMM accumulate (per 256-thread k-group) ----------------
// Output tile: 32 rows x 16 cols x NG gates. Group handles k in [kBase, kBase+Kh).
template<int NG>
__device__ __forceinline__ void gemm_pipe(
    const float* __restrict__ A, int lda,
    const float* __restrict__ W, int ldw,
    int kBase, int Kh,
    int rowBase, int colBase,
    u64 (&ar)[2], u64 (&az)[2], u64 (&an)[2],
    SmG& sg, int grp)
{
    const int t2   = threadIdx.x & 255;
    const int lane = t2 & 31, warp = t2 >> 5;
    const int cL = (warp & 1) * 8 + (lane & 7);
    const int rL = (warp >> 1) * 8 + (lane >> 3) * 2;
    (void)cL; (void)rL;

    const int hR  = t2 >> 3;
    const int hK  = (t2 & 7) << 2;
    const int wr0 = t2 >> 3;
    const int wk  = (t2 & 7) << 2;
    const int wr1 = 32 + (t2 >> 3);
    const bool w0ok = (NG == 3) || (t2 < 128);
    const bool w1ok = (NG == 3) && (t2 < 128);

    const size_t hOff = (size_t)(rowBase + hR) * lda + kBase + hK;
    size_t wOff0 = 0, wOff1 = 0;
    if (w0ok) wOff0 = (size_t)((wr0 >> 4) * HDIM + colBase + (wr0 & 15)) * ldw + kBase + wk;
    if (w1ok) wOff1 = (size_t)((wr1 >> 4) * HDIM + colBase + (wr1 & 15)) * ldw + kBase + wk;

    const int nt = Kh >> 5;
    float4 pfH, pfW0, pfW1;

#define GLD(kt) { int k0 = (kt) << 5;                                   \
        pfH = *(const float4*)(A + hOff + k0);                          \
        if (w0ok) pfW0 = *(const float4*)(W + wOff0 + k0);              \
        if (w1ok) pfW1 = *(const float4*)(W + wOff1 + k0); }
#define GST(b) { *(float4*)&sg.hs[b][hR][hK] = pfH;                     \
        if (w0ok) *(float4*)&sg.ws[b][wr0][wk] = pfW0;                  \
        if (w1ok) *(float4*)&sg.ws[b][wr1][wk] = pfW1; }

    GLD(0); GST(0);
    if (nt > 1) GLD(1);
    barg(grp);

    for (int kt = 0; kt < nt; kt++) {
        const int cur = kt & 1;
        if (kt + 1 < nt) GST(cur ^ 1);
        if (kt + 2 < nt) GLD(kt + 2);
        #pragma unroll
        for (int kk = 0; kk < 32; kk += 4) {
            ulonglong2 wr = *(const ulonglong2*)&sg.ws[cur][cL][kk];
            ulonglong2 wz, wn;
            if (NG == 3) {
                wz = *(const ulonglong2*)&sg.ws[cur][16 + cL][kk];
                wn = *(const ulonglong2*)&sg.ws[cur][32 + cL][kk];
            }
            #pragma unroll
            for (int i = 0; i < 2; i++) {
                ulonglong2 h = *(const ulonglong2*)&sg.hs[cur][rL + i][kk];
                ar[i] = fma2(h.x, wr.x, ar[i]);
                ar[i] = fma2(h.y, wr.y, ar[i]);
                if (NG == 3) {
                    az[i] = fma2(h.x, wz.x, az[i]);
                    az[i] = fma2(h.y, wz.y, az[i]);
                    an[i] = fma2(h.x, wn.x, an[i]);
                    an[i] = fma2(h.y, wn.y, an[i]);
                }
            }
        }
        barg(grp);
    }
#undef GLD
#undef GST
}

// ---------------- one GRU output tile: 32 rows x 16 cols (512 threads, k-split) ----------------
__device__ void gru_tile(const float* __restrict__ h_in,
                         const float* __restrict__ Whh,
                         const float* __restrict__ bhh,
                         const float* __restrict__ xin,
                         int ldx, int KIN,
                         const float* __restrict__ Wih,
                         const float* __restrict__ bih,
                         float* __restrict__ h_out,
                         int rowBase, int colBase, SmU& sm)
{
    const int tid = threadIdx.x;
    const int t2  = tid & 255;
    const int grp = tid >> 8;
    const int lane = t2 & 31, warp = t2 >> 5;
    const int cL = (warp & 1) * 8 + (lane & 7);
    const int rL = (warp >> 1) * 8 + (lane >> 3) * 2;
    const int col = colBase + cL;

    u64 ar[2] = {0,0}, az[2] = {0,0}, ahn[2] = {0,0}, ain[2] = {0,0};
    float xr[2] = {0.f,0.f}, xz[2] = {0.f,0.f}, xn[2] = {0.f,0.f};

    if (h_in)
        gemm_pipe<3>(h_in, HDIM, Whh, HDIM, grp*(HDIM/2), HDIM/2,
                     rowBase, colBase, ar, az, ahn, sm.p.g[grp], grp);

    if (KIN >= 32) {
        gemm_pipe<3>(xin, ldx, Wih, KIN, grp*(KIN/2), KIN/2,
                     rowBase, colBase, ar, az, ain, sm.p.g[grp], grp);
    } else if (grp == 0) {
        for (int k = 0; k < KIN; k++) {
            float wr = Wih[(size_t)(0*HDIM + col)*KIN + k];
            float wz = Wih[(size_t)(1*HDIM + col)*KIN + k];
            float wn = Wih[(size_t)(2*HDIM + col)*KIN + k];
            #pragma unroll
            for (int i = 0; i < 2; i++) {
                float xv = xin[(size_t)(rowBase + rL + i)*ldx + k];
                xr[i] = fmaf(xv, wr, xr[i]);
                xz[i] = fmaf(xv, wz, xz[i]);
                xn[i] = fmaf(xv, wn, xn[i]);
            }
        }
    }

    __syncthreads();
    if (grp == 1) {
        u64* d = sm.c.acc[t2];
        d[0] = ar[0]; d[1] = ar[1];
        d[2] = az[0]; d[3] = az[1];
        d[4] = ahn[0]; d[5] = ahn[1];
        d[6] = ain[0]; d[7] = ain[1];
    }
    __syncthreads();
    if (grp == 0) {
        const u64* d = sm.c.acc[t2];
        ar[0]  = add2(ar[0],  d[0]); ar[1]  = add2(ar[1],  d[1]);
        az[0]  = add2(az[0],  d[2]); az[1]  = add2(az[1],  d[3]);
        ahn[0] = add2(ahn[0], d[4]); ahn[1] = add2(ahn[1], d[5]);
        ain[0] = add2(ain[0], d[6]); ain[1] = add2(ain[1], d[7]);

        const float bhr = bhh[col], bhz = bhh[HDIM+col], bhn = bhh[2*HDIM+col];
        const float bir = bih[col], biz = bih[HDIM+col], bin = bih[2*HDIM+col];

        #pragma unroll
        for (int i = 0; i < 2; i++) {
            int row = rowBase + rL + i;
            float accr = red2(ar[i]) + xr[i] + bhr + bir;
            float accz = red2(az[i]) + xz[i] + bhz + biz;
            float hnv  = red2(ahn[i]) + bhn;
            float inv  = red2(ain[i]) + xn[i] + bin;
            float r = 1.f / (1.f + expf(-accr));
            float z = 1.f / (1.f + expf(-accz));
            float n = tanhf(inv + r * hnv);
            float hp = h_in ? h_in[(size_t)row*HDIM + col] : 0.f;
            h_out[(size_t)row*HDIM + col] = (1.f - z) * n + z * hp;
        }
    }
    __syncthreads();
}

// ---------------- linear tile: out = A @ W.T + b ----------------
__device__ void linear_tile(const float* __restrict__ A,
                            const float* __restrict__ W,
                            const float* __restrict__ bias,
                            float* __restrict__ out,
                            int rowBase, int colBase, SmU& sm)
{
    const int tid = threadIdx.x;
    const int t2  = tid & 255;
    const int grp = tid >> 8;
    const int lane = t2 & 31, warp = t2 >> 5;
    const int cL = (warp & 1) * 8 + (lane & 7);
    const int rL = (warp >> 1) * 8 + (lane >> 3) * 2;

    u64 acc[2] = {0,0}, d1[2] = {0,0}, d2[2] = {0,0};
    gemm_pipe<1>(A, HDIM, W, HDIM, grp*(HDIM/2), HDIM/2,
                 rowBase, colBase, acc, d1, d2, sm.p.g[grp], grp);

    __syncthreads();
    if (grp == 1) {
        u64* d = sm.c.acc[t2];
        d[0] = acc[0]; d[1] = acc[1];
    }
    __syncthreads();
    if (grp == 0) {
        const u64* d = sm.c.acc[t2];
        acc[0] = add2(acc[0], d[0]);
        acc[1] = add2(acc[1], d[1]);
        float bb = bias[colBase + cL];
        #pragma unroll
        for (int i = 0; i < 2; i++)
            out[(size_t)(rowBase + rL + i)*HDIM + colBase + cL] = red2(acc[i]) + bb;
    }
    __syncthreads();
}

// ---------------- attention for one batch row (512 threads) ----------------
__device__ void attn_row(int b, int t,
                         const float* __restrict__ query,
                         const float* __restrict__ enc,
                         const float* __restrict__ emb,
                         const int*   __restrict__ tokp,
                         float* __restrict__ rnn_in,
                         float* __restrict__ att_out,
                         SmA& sa)
{
    const int tid = threadIdx.x;
    const int warp = tid >> 5, lane = tid & 31;

    sa.q[tid] = query[(size_t)b*HDIM + tid];
    __syncthreads();

    const float* encb = enc + (size_t)b*HDIM;
    for (int tt = warp; tt < TIN; tt += 16) {
        const float* e = encb + (size_t)tt*BH;
        float s = 0.f;
        #pragma unroll
        for (int k = lane; k < HDIM; k += 32) s = fmaf(sa.q[k], e[k], s);
        #pragma unroll
        for (int o = 16; o; o >>= 1) s += __shfl_xor_sync(0xffffffffu, s, o);
        if (!lane) sa.sc[tt] = s;
    }
    __syncthreads();

    if (tid < 256) {
        float v = sa.sc[tid];
        float m = v;
        #pragma unroll
        for (int o = 16; o; o >>= 1) m = fmaxf(m, __shfl_xor_sync(0xffffffffu, m, o));
        if (!lane) sa.red[warp] = m;
    }
    __syncthreads();
    float gm = sa.red[0];
    #pragma unroll
    for (int i = 1; i < 8; i++) gm = fmaxf(gm, sa.red[i]);
    __syncthreads();
    if (tid < 256) {
        float v = sa.sc[tid];
        float e = expf(v - gm);
        float s = e;
        #pragma unroll
        for (int o = 16; o; o >>= 1) s += __shfl_xor_sync(0xffffffffu, s, o);
        if (!lane) sa.red[8 + warp] = s;
        sa.sc[tid] = e;   // store exp; normalize after total known
    }
    __syncthreads();
    float tot = 0.f;
    #pragma unroll
    for (int i = 0; i < 8; i++) tot += sa.red[8 + i];
    float inv_tot = 1.f / tot;
    if (tid < 256) {
        float w = sa.sc[tid] * inv_tot;
        sa.sc[tid] = w;
        att_out[(size_t)b*MLEN*TIN + (size_t)t*TIN + tid] = w;
    }
    __syncthreads();

    // context: thread owns dim d = tid (512 dims)
    float c = 0.f;
    #pragma unroll 4
    for (int tt = 0; tt < TIN; tt++)
        c = fmaf(sa.sc[tt], encb[(size_t)tt*BH + tid], c);
    float* rb = rnn_in + (size_t)b*1024;
    rb[512 + tid] = c;

    const int tk = tokp[b];
    rb[tid] = emb[(size_t)tk*HDIM + tid];
    __syncthreads();
}

// ---------------- logits + argmax for one batch row (512 threads) ----------------
__device__ void logits_row(int b, int t,
                           const float* __restrict__ g1,
                           const float* __restrict__ outW,
                           const float* __restrict__ outb,
                           float* __restrict__ vec_out,
                           int* __restrict__ tok_next,
                           SmL& sl)
{
    const int tid = threadIdx.x;
    const int warp = tid >> 5, lane = tid & 31;

    sl.hrow[tid] = g1[(size_t)b*HDIM + tid];
    __syncthreads();

    for (int v = warp; v < VOC; v += 16) {
        const float* wrow = outW + (size_t)v*HDIM;
        float s = 0.f;
        #pragma unroll
        for (int k = lane; k < HDIM; k += 32) s = fmaf(sl.hrow[k], wrow[k], s);
        #pragma unroll
        for (int o = 16; o; o >>= 1) s += __shfl_xor_sync(0xffffffffu, s, o);
        if (!lane) {
            s += outb[v];
            sl.lg[v] = s;
            vec_out[(size_t)b*MLEN*VOC + (size_t)t*VOC + v] = s;
        }
    }
    __syncthreads();
    if (tid == 0) {
        int best = 0; float bv = sl.lg[0];
        #pragma unroll
        for (int v = 1; v < VOC; v++)
            if (sl.lg[v] > bv) { bv = sl.lg[v]; best = v; }
        tok_next[b] = best;
    }
    __syncthreads();
}

// ---------------- init kernel ----------------
__global__ void init_kernel()
{
    if (threadIdx.x == 0) { g_arrive = 0; g_release = 0; }
    g_tok[threadIdx.x] = 0;
}

// ---------------- persistent megakernel ----------------
__global__ void __launch_bounds__(NTHR, 1)
mega_kernel(const float* __restrict__ x,
            const float* __restrict__ emb,
            const float* __restrict__ eWih0, const float* __restrict__ eWhh0,
            const float* __restrict__ ebih0, const float* __restrict__ ebhh0,
            const float* __restrict__ eWih1, const float* __restrict__ eWhh1,
            const float* __restrict__ ebih1, const float* __restrict__ ebhh1,
            const float* __restrict__ dWih0, const float* __restrict__ dWhh0,
            const float* __restrict__ dbih0, const float* __restrict__ dbhh0,
            const float* __restrict__ dWih1, const float* __restrict__ dWhh1,
            const float* __restrict__ dbih1, const float* __restrict__ dbhh1,
            const float* __restrict__ qW,    const float* __restrict__ qb,
            const float* __restrict__ outW,  const float* __restrict__ outb,
            float* __restrict__ vec_out,
            float* __restrict__ hid_out,
            float* __restrict__ att_out)
{
    __shared__ SmU sm;
    unsigned phase = 0;
    const int bid = blockIdx.x;

    // ---------- encoder: layer0[s] and layer1[s-1] pipelined ----------
    for (int s = 0; s <= TIN; s++) {
        for (int u = bid; u < 256; u += NBLK) {
            int tile = u & 127;
            int rowBase = (tile >> 5) * 32;
            int colBase = (tile & 31) * 16;
            if (u < 128) {
                if (s < TIN) {
                    const float* hprev = s ? (g_y0 + (size_t)(s-1)*BH) : nullptr;
                    gru_tile(hprev, eWhh0, ebhh0,
                             x + (size_t)s*2, TIN*2, 2, eWih0, ebih0,
                             g_y0 + (size_t)s*BH, rowBase, colBase, sm);
                }
            } else {
                if (s >= 1) {
                    int t = s - 1;
                    const float* hprev = t ? (g_enc + (size_t)(t-1)*BH) : nullptr;
                    gru_tile(hprev, eWhh1, ebhh1,
                             g_y0 + (size_t)t*BH, HDIM, HDIM, eWih1, ebih1,
                             g_enc + (size_t)t*BH, rowBase, colBase, sm);
                }
            }
        }
        gsync(phase);
    }

    // ---------- decoder ----------
    for (int u = bid; u < 128; u += NBLK) {
        int rowBase = (u >> 5) * 32;
        int colBase = (u & 31) * 16;
        linear_tile(g_enc + (size_t)(TIN-1)*BH, qW, qb, g_q, rowBase, colBase, sm);
    }
    gsync(phase);

    for (int t = 0; t < MLEN; t++) {
        const float* h0prev = t ? (g_h0 + (size_t)(t-1)*BH) : (g_y0  + (size_t)(TIN-1)*BH);
        const float* h1prev = t ? (g_h1 + (size_t)(t-1)*BH) : (g_enc + (size_t)(TIN-1)*BH);

        // Ph_b: attention -> rnn_in[t]
        for (int u = bid; u < BSZ; u += NBLK)
            attn_row(u, t, g_q + (size_t)t*BH, g_enc, emb,
                     g_tok + (size_t)t*BSZ, g_rnn + (size_t)t*B2H, att_out, sm.a);
        gsync(phase);

        // Ph_c: decoder gru0 (hidden K=512 + input K=1024)
        for (int u = bid; u < 128; u += NBLK) {
            int rowBase = (u >> 5) * 32;
            int colBase = (u & 31) * 16;
            gru_tile(h0prev, dWhh0, dbhh0,
                     g_rnn + (size_t)t*B2H, 2*HDIM, 2*HDIM, dWih0, dbih0,
                     g_h0 + (size_t)t*BH, rowBase, colBase, sm);
        }
        gsync(phase);

        // Ph_d: decoder gru1
        for (int u = bid; u < 128; u += NBLK) {
            int rowBase = (u >> 5) * 32;
            int colBase = (u & 31) * 16;
            gru_tile(h1prev, dWhh1, dbhh1,
                     g_h0 + (size_t)t*BH, HDIM, HDIM, dWih1, dbih1,
                     g_h1 + (size_t)t*BH, rowBase, colBase, sm);
        }
        gsync(phase);

        // Ph_e: logits+argmax (0..127) and next-step query (128..255)
        for (int u = bid; u < 256; u += NBLK) {
            if (u < 128) {
                logits_row(u, t, g_h1 + (size_t)t*BH, outW, outb,
                           vec_out, g_tok + (size_t)(t+1)*BSZ, sm.l);
            } else if (t + 1 < MLEN) {
                int tile = u - 128;
                int rowBase = (tile >> 5) * 32;
                int colBase = (tile & 31) * 16;
                linear_tile(g_h1 + (size_t)t*BH, qW, qb,
                            g_q + (size_t)(t+1)*BH, rowBase, colBase, sm);
            }
        }
        gsync(phase);
    }

    // ---------- final hidden copy ----------
    for (int i = bid*NTHR + threadIdx.x; i < BH; i += NBLK*NTHR) {
        hid_out[i]      = g_h0[(size_t)(MLEN-1)*BH + i];
        hid_out[BH + i] = g_h1[(size_t)(MLEN-1)*BH + i];
    }
}

// ---------------- host ----------------
extern "C" void kernel_launch(void* const* d_in, const int* in_sizes, int n_in,
                              void* d_out, int out_size)
{
    const float* x     = (const float*)d_in[0];
    const float* emb   = (const float*)d_in[1];
    const float* eWih0 = (const float*)d_in[2];
    const float* eWhh0 = (const float*)d_in[3];
    const float* ebih0 = (const float*)d_in[4];
    const float* ebhh0 = (const float*)d_in[5];
    const float* eWih1 = (const float*)d_in[6];
    const float* eWhh1 = (const float*)d_in[7];
    const float* ebih1 = (const float*)d_in[8];
    const float* ebhh1 = (const float*)d_in[9];
    const float* dWih0 = (const float*)d_in[10];
    const float* dWhh0 = (const float*)d_in[11];
    const float* dbih0 = (const float*)d_in[12];
    const float* dbhh0 = (const float*)d_in[13];
    const float* dWih1 = (const float*)d_in[14];
    const float* dWhh1 = (const float*)d_in[15];
    const float* dbih1 = (const float*)d_in[16];
    const float* dbhh1 = (const float*)d_in[17];
    const float* qW    = (const float*)d_in[18];
    const float* qb    = (const float*)d_in[19];
    const float* outW  = (const float*)d_in[20];
    const float* outb  = (const float*)d_in[21];

    float* out     = (float*)d_out;
    float* vec_out = out;
    float* hid_out = out + (size_t)BSZ*MLEN*VOC;
    float* att_out = hid_out + 2*BH;

    init_kernel<<<1, BSZ>>>();
    mega_kernel<<<NBLK, NTHR>>>(x, emb,
                                eWih0, eWhh0, ebih0, ebhh0,
                                eWih1, eWhh1, ebih1, ebhh1,
                                dWih0, dWhh0, dbih0, dbhh0,
                                dWih1, dWhh1, dbih1, dbhh1,
                                qW, qb, outW, outb,
                                vec_out, hid_out, att_out);
}

// round 8
// speedup vs baseline: 1.1212x; 1.1212x over previous
#include <cuda_runtime.h>
#include <math.h>

#define HDIM 512
#define BSZ  128
#define TIN  256
#define MLEN 128
#define VOC  32
#define BH   (BSZ*HDIM)
#define B2H  (BSZ*2*HDIM)
#define NBLK 148
#define NTHR 512

typedef unsigned long long u64;

// ---------------- device scratch ----------------
__device__ float g_y0[TIN*BH];
__device__ float g_enc[TIN*BH];
__device__ float g_q[MLEN*BH];
__device__ float g_rnn[MLEN*B2H];
__device__ float g_h0[MLEN*BH];
__device__ float g_h1[MLEN*BH];
__device__ int   g_tok[(MLEN+1)*BSZ];
__device__ unsigned g_arrive;
__device__ volatile unsigned g_release;

// ---------------- shared memory ----------------
struct SmSlice { float hs[2][32][36]; float ws[2][48][36]; };   // 23040 B
struct SmA { float q[HDIM]; float sc[TIN]; float red[16]; };
struct SmL { float hrow[HDIM]; float lg[VOC]; };
union SmAll {
    SmSlice sl[4];            // 92160 B
    u64 comb[3][128][16];     // 49152 B (used only after GEMMs complete)
    SmA a;
    SmL l;
};

// ---------------- packed f32x2 helpers ----------------
__device__ __forceinline__ u64 fma2(u64 a, u64 b, u64 c)
{
    u64 d;
    asm("fma.rn.f32x2 %0, %1, %2, %3;" : "=l"(d) : "l"(a), "l"(b), "l"(c));
    return d;
}
__device__ __forceinline__ u64 add2(u64 a, u64 b)
{
    u64 d;
    asm("add.rn.f32x2 %0, %1, %2;" : "=l"(d) : "l"(a), "l"(b));
    return d;
}
__device__ __forceinline__ float red2(u64 a)
{
    float lo, hi;
    asm("mov.b64 {%0, %1}, %2;" : "=f"(lo), "=f"(hi) : "l"(a));
    return lo + hi;
}

// named barrier for one 128-thread k-slice (ids 1..4)
__device__ __forceinline__ void barg(int slice)
{
    asm volatile("bar.sync %0, %1;" :: "r"(slice + 1), "r"(128) : "memory");
}

// ---------------- software grid barrier ----------------
__device__ __forceinline__ void gsync(unsigned &phase)
{
    __threadfence();
    __syncthreads();
    phase++;
    if (threadIdx.x == 0) {
        unsigned p = phase;
        unsigned old = atomicAdd(&g_arrive, 1u);
        if (old == p * (unsigned)NBLK - 1u) {
            g_release = p;
        } else {
            while (g_release < p) { }
        }
        __threadfence();
    }
    __syncthreads();
}

// ---------------- pipelined K-major GEMM accumulate (per 128-thread k-slice) ----------------
// Output tile: 32 rows x 16 cols x NG gates. Slice handles k in [kBase, kBase+Kh).
// Thread t1: col = t1&15, rows (t1>>4)*4 .. +3.  Accumulators: aG[gate][4 rows] f32x2.
template<int NG>
__device__ __forceinline__ void gemm_pipe(
    const float* __restrict__ A, int lda,
    const float* __restrict__ W, int ldw,
    int kBase, int Kh, int rowBase, int colBase,
    u64 (&a0)[4], u64 (&a1)[4], u64 (&a2)[4],
    SmSlice& sg, int slice)
{
    const int t1  = threadIdx.x & 127;
    const int cL  = t1 & 15;
    const int rG  = t1 >> 4;           // 0..7

    // load mapping: 128 threads move 256 h-float4 (2 each) + NG*128 w-float4
    const int ldR = t1 >> 3;           // 0..15
    const int ldK = (t1 & 7) << 2;     // 0,4,...,28

    const size_t hOffA = (size_t)(rowBase + ldR) * lda + kBase + ldK;
    const size_t hOffB = (size_t)(rowBase + 16 + ldR) * lda + kBase + ldK;
    // w load i covers gate i, col ldR
    const size_t wOff0 = (size_t)(0*HDIM + colBase + ldR) * ldw + kBase + ldK;
    const size_t wOff1 = (size_t)(1*HDIM + colBase + ldR) * ldw + kBase + ldK;
    const size_t wOff2 = (size_t)(2*HDIM + colBase + ldR) * ldw + kBase + ldK;

    const int nt = Kh >> 5;
    float4 pH0, pH1, pW0, pW1, pW2;

#define GLD(kt) do { int k0_ = (kt) << 5;                               \
        pH0 = *(const float4*)(A + hOffA + k0_);                        \
        pH1 = *(const float4*)(A + hOffB + k0_);                        \
        pW0 = *(const float4*)(W + wOff0 + k0_);                        \
        if (NG >= 2) pW1 = *(const float4*)(W + wOff1 + k0_);           \
        if (NG >= 3) pW2 = *(const float4*)(W + wOff2 + k0_);           \
    } while (0)
#define GST(b) do {                                                     \
        *(float4*)&sg.hs[b][ldR][ldK]      = pH0;                       \
        *(float4*)&sg.hs[b][16+ldR][ldK]   = pH1;                       \
        *(float4*)&sg.ws[b][ldR][ldK]      = pW0;                       \
        if (NG >= 2) *(float4*)&sg.ws[b][16+ldR][ldK] = pW1;            \
        if (NG >= 3) *(float4*)&sg.ws[b][32+ldR][ldK] = pW2;            \
    } while (0)

    GLD(0); GST(0);
    if (nt > 1) GLD(1);
    barg(slice);

    for (int kt = 0; kt < nt; kt++) {
        const int cur = kt & 1;
        if (kt + 1 < nt) GST(cur ^ 1);
        if (kt + 2 < nt) GLD(kt + 2);
        #pragma unroll
        for (int kk = 0; kk < 32; kk += 4) {
            ulonglong2 w0 = *(const ulonglong2*)&sg.ws[cur][cL][kk];
            ulonglong2 w1, w2;
            if (NG >= 2) w1 = *(const ulonglong2*)&sg.ws[cur][16 + cL][kk];
            if (NG >= 3) w2 = *(const ulonglong2*)&sg.ws[cur][32 + cL][kk];
            #pragma unroll
            for (int i = 0; i < 4; i++) {
                ulonglong2 h = *(const ulonglong2*)&sg.hs[cur][rG*4 + i][kk];
                a0[i] = fma2(h.x, w0.x, a0[i]);
                a0[i] = fma2(h.y, w0.y, a0[i]);
                if (NG >= 2) { a1[i] = fma2(h.x, w1.x, a1[i]);
                               a1[i] = fma2(h.y, w1.y, a1[i]); }
                if (NG >= 3) { a2[i] = fma2(h.x, w2.x, a2[i]);
                               a2[i] = fma2(h.y, w2.y, a2[i]); }
            }
        }
        barg(slice);
    }
#undef GLD
#undef GST
}

// ---------------- one GRU output tile: 32 rows x 16 cols (512 threads, 4-way k-split) ----------------
__device__ void gru_tile(const float* __restrict__ h_in,
                         const float* __restrict__ Whh,
                         const float* __restrict__ bhh,
                         const float* __restrict__ xin,
                         int ldx, int KIN,
                         const float* __restrict__ Wih,
                         const float* __restrict__ bih,
                         float* __restrict__ h_out,
                         int rowBase, int colBase, SmAll& sm)
{
    const int tid   = threadIdx.x;
    const int t1    = tid & 127;
    const int slice = tid >> 7;
    const int cL    = t1 & 15;
    const int rG    = t1 >> 4;
    const int col   = colBase + cL;

    u64 ar[4] = {0,0,0,0}, az[4] = {0,0,0,0};
    u64 ahn[4] = {0,0,0,0}, ain[4] = {0,0,0,0};
    float xr[4] = {0.f,0.f,0.f,0.f}, xz[4] = {0.f,0.f,0.f,0.f}, xn[4] = {0.f,0.f,0.f,0.f};

    if (h_in)
        gemm_pipe<3>(h_in, HDIM, Whh, HDIM, slice*(HDIM/4), HDIM/4,
                     rowBase, colBase, ar, az, ahn, sm.sl[slice], slice);

    if (KIN >= 32) {
        const int Kq = KIN / 4;
        gemm_pipe<3>(xin, ldx, Wih, KIN, slice*Kq, Kq,
                     rowBase, colBase, ar, az, ain, sm.sl[slice], slice);
    } else if (slice == 0) {
        for (int k = 0; k < KIN; k++) {
            float wr = Wih[(size_t)(0*HDIM + col)*KIN + k];
            float wz = Wih[(size_t)(1*HDIM + col)*KIN + k];
            float wn = Wih[(size_t)(2*HDIM + col)*KIN + k];
            #pragma unroll
            for (int i = 0; i < 4; i++) {
                float xv = xin[(size_t)(rowBase + rG*4 + i)*ldx + k];
                xr[i] = fmaf(xv, wr, xr[i]);
                xz[i] = fmaf(xv, wz, xz[i]);
                xn[i] = fmaf(xv, wn, xn[i]);
            }
        }
    }

    __syncthreads();
    if (slice) {
        u64* d = sm.comb[slice-1][t1];
        #pragma unroll
        for (int i = 0; i < 4; i++) {
            d[i]      = ar[i];
            d[4 + i]  = az[i];
            d[8 + i]  = ahn[i];
            d[12 + i] = ain[i];
        }
    }
    __syncthreads();
    if (slice == 0) {
        #pragma unroll
        for (int s = 0; s < 3; s++) {
            const u64* d = sm.comb[s][t1];
            #pragma unroll
            for (int i = 0; i < 4; i++) {
                ar[i]  = add2(ar[i],  d[i]);
                az[i]  = add2(az[i],  d[4 + i]);
                ahn[i] = add2(ahn[i], d[8 + i]);
                ain[i] = add2(ain[i], d[12 + i]);
            }
        }

        const float bhr = bhh[col], bhz = bhh[HDIM+col], bhn = bhh[2*HDIM+col];
        const float bir = bih[col], biz = bih[HDIM+col], bin = bih[2*HDIM+col];

        #pragma unroll
        for (int i = 0; i < 4; i++) {
            int row = rowBase + rG*4 + i;
            float accr = red2(ar[i]) + xr[i] + bhr + bir;
            float accz = red2(az[i]) + xz[i] + bhz + biz;
            float hnv  = red2(ahn[i]) + bhn;
            float inv  = red2(ain[i]) + xn[i] + bin;
            float r = 1.f / (1.f + expf(-accr));
            float z = 1.f / (1.f + expf(-accz));
            float n = tanhf(inv + r * hnv);
            float hp = h_in ? h_in[(size_t)row*HDIM + col] : 0.f;
            h_out[(size_t)row*HDIM + col] = (1.f - z) * n + z * hp;
        }
    }
    __syncthreads();
}

// ---------------- linear tile: out = A @ W.T + b (512 threads, 4-way k-split) ----------------
__device__ void linear_tile(const float* __restrict__ A,
                            const float* __restrict__ W,
                            const float* __restrict__ bias,
                            float* __restrict__ out,
                            int rowBase, int colBase, SmAll& sm)
{
    const int tid   = threadIdx.x;
    const int t1    = tid & 127;
    const int slice = tid >> 7;
    const int cL    = t1 & 15;
    const int rG    = t1 >> 4;

    u64 acc[4] = {0,0,0,0}, d1[4] = {0,0,0,0}, d2[4] = {0,0,0,0};
    gemm_pipe<1>(A, HDIM, W, HDIM, slice*(HDIM/4), HDIM/4,
                 rowBase, colBase, acc, d1, d2, sm.sl[slice], slice);

    __syncthreads();
    if (slice) {
        u64* d = sm.comb[slice-1][t1];
        #pragma unroll
        for (int i = 0; i < 4; i++) d[i] = acc[i];
    }
    __syncthreads();
    if (slice == 0) {
        #pragma unroll
        for (int s = 0; s < 3; s++) {
            const u64* d = sm.comb[s][t1];
            #pragma unroll
            for (int i = 0; i < 4; i++) acc[i] = add2(acc[i], d[i]);
        }
        float bb = bias[colBase + cL];
        #pragma unroll
        for (int i = 0; i < 4; i++)
            out[(size_t)(rowBase + rG*4 + i)*HDIM + colBase + cL] = red2(acc[i]) + bb;
    }
    __syncthreads();
}

// ---------------- attention for one batch row (512 threads) ----------------
__device__ void attn_row(int b, int t,
                         const float* __restrict__ query,
                         const float* __restrict__ enc,
                         const float* __restrict__ emb,
                         const int*   __restrict__ tokp,
                         float* __restrict__ rnn_in,
                         float* __restrict__ att_out,
                         SmA& sa)
{
    const int tid = threadIdx.x;
    const int warp = tid >> 5, lane = tid & 31;

    sa.q[tid] = query[(size_t)b*HDIM + tid];
    __syncthreads();

    const float* encb = enc + (size_t)b*HDIM;
    for (int tt = warp; tt < TIN; tt += 16) {
        const float* e = encb + (size_t)tt*BH;
        float s = 0.f;
        #pragma unroll
        for (int k = lane; k < HDIM; k += 32) s = fmaf(sa.q[k], e[k], s);
        #pragma unroll
        for (int o = 16; o; o >>= 1) s += __shfl_xor_sync(0xffffffffu, s, o);
        if (!lane) sa.sc[tt] = s;
    }
    __syncthreads();

    if (tid < 256) {
        float v = sa.sc[tid];
        float m = v;
        #pragma unroll
        for (int o = 16; o; o >>= 1) m = fmaxf(m, __shfl_xor_sync(0xffffffffu, m, o));
        if (!lane) sa.red[warp] = m;
    }
    __syncthreads();
    float gm = sa.red[0];
    #pragma unroll
    for (int i = 1; i < 8; i++) gm = fmaxf(gm, sa.red[i]);
    __syncthreads();
    if (tid < 256) {
        float v = sa.sc[tid];
        float e = expf(v - gm);
        float s = e;
        #pragma unroll
        for (int o = 16; o; o >>= 1) s += __shfl_xor_sync(0xffffffffu, s, o);
        if (!lane) sa.red[8 + warp] = s;
        sa.sc[tid] = e;
    }
    __syncthreads();
    float tot = 0.f;
    #pragma unroll
    for (int i = 0; i < 8; i++) tot += sa.red[8 + i];
    float inv_tot = 1.f / tot;
    if (tid < 256) {
        float w = sa.sc[tid] * inv_tot;
        sa.sc[tid] = w;
        att_out[(size_t)b*MLEN*TIN + (size_t)t*TIN + tid] = w;
    }
    __syncthreads();

    float c = 0.f;
    #pragma unroll 4
    for (int tt = 0; tt < TIN; tt++)
        c = fmaf(sa.sc[tt], encb[(size_t)tt*BH + tid], c);
    float* rb = rnn_in + (size_t)b*1024;
    rb[512 + tid] = c;

    const int tk = tokp[b];
    rb[tid] = emb[(size_t)tk*HDIM + tid];
    __syncthreads();
}

// ---------------- logits + argmax for one batch row (512 threads) ----------------
__device__ void logits_row(int b, int t,
                           const float* __restrict__ g1,
                           const float* __restrict__ outW,
                           const float* __restrict__ outb,
                           float* __restrict__ vec_out,
                           int* __restrict__ tok_next,
                           SmL& sl)
{
    const int tid = threadIdx.x;
    const int warp = tid >> 5, lane = tid & 31;

    sl.hrow[tid] = g1[(size_t)b*HDIM + tid];
    __syncthreads();

    for (int v = warp; v < VOC; v += 16) {
        const float* wrow = outW + (size_t)v*HDIM;
        float s = 0.f;
        #pragma unroll
        for (int k = lane; k < HDIM; k += 32) s = fmaf(sl.hrow[k], wrow[k], s);
        #pragma unroll
        for (int o = 16; o; o >>= 1) s += __shfl_xor_sync(0xffffffffu, s, o);
        if (!lane) {
            s += outb[v];
            sl.lg[v] = s;
            vec_out[(size_t)b*MLEN*VOC + (size_t)t*VOC + v] = s;
        }
    }
    __syncthreads();
    if (tid == 0) {
        int best = 0; float bv = sl.lg[0];
        #pragma unroll
        for (int v = 1; v < VOC; v++)
            if (sl.lg[v] > bv) { bv = sl.lg[v]; best = v; }
        tok_next[b] = best;
    }
    __syncthreads();
}

// ---------------- init kernel ----------------
__global__ void init_kernel()
{
    if (threadIdx.x == 0) { g_arrive = 0; g_release = 0; }
    g_tok[threadIdx.x] = 0;
}

// ---------------- persistent megakernel ----------------
__global__ void __launch_bounds__(NTHR, 1)
mega_kernel(const float* __restrict__ x,
            const float* __restrict__ emb,
            const float* __restrict__ eWih0, const float* __restrict__ eWhh0,
            const float* __restrict__ ebih0, const float* __restrict__ ebhh0,
            const float* __restrict__ eWih1, const float* __restrict__ eWhh1,
            const float* __restrict__ ebih1, const float* __restrict__ ebhh1,
            const float* __restrict__ dWih0, const float* __restrict__ dWhh0,
            const float* __restrict__ dbih0, const float* __restrict__ dbhh0,
            const float* __restrict__ dWih1, const float* __restrict__ dWhh1,
            const float* __restrict__ dbih1, const float* __restrict__ dbhh1,
            const float* __restrict__ qW,    const float* __restrict__ qb,
            const float* __restrict__ outW,  const float* __restrict__ outb,
            float* __restrict__ vec_out,
            float* __restrict__ hid_out,
            float* __restrict__ att_out)
{
    extern __shared__ unsigned char smraw[];
    SmAll& sm = *reinterpret_cast<SmAll*>(smraw);
    unsigned phase = 0;
    const int bid = blockIdx.x;

    // ---------- encoder: layer0[s] and layer1[s-1] pipelined ----------
    for (int s = 0; s <= TIN; s++) {
        for (int u = bid; u < 256; u += NBLK) {
            int tile = u & 127;
            int rowBase = (tile >> 5) * 32;
            int colBase = (tile & 31) * 16;
            if (u < 128) {
                if (s < TIN) {
                    const float* hprev = s ? (g_y0 + (size_t)(s-1)*BH) : nullptr;
                    gru_tile(hprev, eWhh0, ebhh0,
                             x + (size_t)s*2, TIN*2, 2, eWih0, ebih0,
                             g_y0 + (size_t)s*BH, rowBase, colBase, sm);
                }
            } else {
                if (s >= 1) {
                    int t = s - 1;
                    const float* hprev = t ? (g_enc + (size_t)(t-1)*BH) : nullptr;
                    gru_tile(hprev, eWhh1, ebhh1,
                             g_y0 + (size_t)t*BH, HDIM, HDIM, eWih1, ebih1,
                             g_enc + (size_t)t*BH, rowBase, colBase, sm);
                }
            }
        }
        gsync(phase);
    }

    // ---------- decoder ----------
    for (int u = bid; u < 128; u += NBLK) {
        int rowBase = (u >> 5) * 32;
        int colBase = (u & 31) * 16;
        linear_tile(g_enc + (size_t)(TIN-1)*BH, qW, qb, g_q, rowBase, colBase, sm);
    }
    gsync(phase);

    for (int t = 0; t < MLEN; t++) {
        const float* h0prev = t ? (g_h0 + (size_t)(t-1)*BH) : (g_y0  + (size_t)(TIN-1)*BH);
        const float* h1prev = t ? (g_h1 + (size_t)(t-1)*BH) : (g_enc + (size_t)(TIN-1)*BH);

        // Ph_b: attention -> rnn_in[t]
        for (int u = bid; u < BSZ; u += NBLK)
            attn_row(u, t, g_q + (size_t)t*BH, g_enc, emb,
                     g_tok + (size_t)t*BSZ, g_rnn + (size_t)t*B2H, att_out, sm.a);
        gsync(phase);

        // Ph_c: decoder gru0 (hidden K=512 + input K=1024)
        for (int u = bid; u < 128; u += NBLK) {
            int rowBase = (u >> 5) * 32;
            int colBase = (u & 31) * 16;
            gru_tile(h0prev, dWhh0, dbhh0,
                     g_rnn + (size_t)t*B2H, 2*HDIM, 2*HDIM, dWih0, dbih0,
                     g_h0 + (size_t)t*BH, rowBase, colBase, sm);
        }
        gsync(phase);

        // Ph_d: decoder gru1
        for (int u = bid; u < 128; u += NBLK) {
            int rowBase = (u >> 5) * 32;
            int colBase = (u & 31) * 16;
            gru_tile(h1prev, dWhh1, dbhh1,
                     g_h0 + (size_t)t*BH, HDIM, HDIM, dWih1, dbih1,
                     g_h1 + (size_t)t*BH, rowBase, colBase, sm);
        }
        gsync(phase);

        // Ph_e: logits+argmax (0..127) and next-step query (128..255)
        for (int u = bid; u < 256; u += NBLK) {
            if (u < 128) {
                logits_row(u, t, g_h1 + (size_t)t*BH, outW, outb,
                           vec_out, g_tok + (size_t)(t+1)*BSZ, sm.l);
            } else if (t + 1 < MLEN) {
                int tile = u - 128;
                int rowBase = (tile >> 5) * 32;
                int colBase = (tile & 31) * 16;
                linear_tile(g_h1 + (size_t)t*BH, qW, qb,
                            g_q + (size_t)(t+1)*BH, rowBase, colBase, sm);
            }
        }
        gsync(phase);
    }

    // ---------- final hidden copy ----------
    for (int i = bid*NTHR + threadIdx.x; i < BH; i += NBLK*NTHR) {
        hid_out[i]      = g_h0[(size_t)(MLEN-1)*BH + i];
        hid_out[BH + i] = g_h1[(size_t)(MLEN-1)*BH + i];
    }
}

// ---------------- host ----------------
extern "C" void kernel_launch(void* const* d_in, const int* in_sizes, int n_in,
                              void* d_out, int out_size)
{
    const float* x     = (const float*)d_in[0];
    const float* emb   = (const float*)d_in[1];
    const float* eWih0 = (const float*)d_in[2];
    const float* eWhh0 = (const float*)d_in[3];
    const float* ebih0 = (const float*)d_in[4];
    const float* ebhh0 = (const float*)d_in[5];
    const float* eWih1 = (const float*)d_in[6];
    const float* eWhh1 = (const float*)d_in[7];
    const float* ebih1 = (const float*)d_in[8];
    const float* ebhh1 = (const float*)d_in[9];
    const float* dWih0 = (const float*)d_in[10];
    const float* dWhh0 = (const float*)d_in[11];
    const float* dbih0 = (const float*)d_in[12];
    const float* dbhh0 = (const float*)d_in[13];
    const float* dWih1 = (const float*)d_in[14];
    const float* dWhh1 = (const float*)d_in[15];
    const float* dbih1 = (const float*)d_in[16];
    const float* dbhh1 = (const float*)d_in[17];
    const float* qW    = (const float*)d_in[18];
    const float* qb    = (const float*)d_in[19];
    const float* outW  = (const float*)d_in[20];
    const float* outb  = (const float*)d_in[21];

    float* out     = (float*)d_out;
    float* vec_out = out;
    float* hid_out = out + (size_t)BSZ*MLEN*VOC;
    float* att_out = hid_out + 2*BH;

    static int smem_set = 0;
    if (!smem_set) {
        cudaFuncSetAttribute(mega_kernel,
                             cudaFuncAttributeMaxDynamicSharedMemorySize,
                             (int)sizeof(SmAll));
        smem_set = 1;
    }

    init_kernel<<<1, BSZ>>>();
    mega_kernel<<<NBLK, NTHR, sizeof(SmAll)>>>(x, emb,
                                eWih0, eWhh0, ebih0, ebhh0,
                                eWih1, eWhh1, ebih1, ebhh1,
                                dWih0, dWhh0, dbih0, dbhh0,
                                dWih1, dWhh1, dbih1, dbhh1,
                                qW, qb, outW, outb,
                                vec_out, hid_out, att_out);
}